// round 16
// baseline (speedup 1.0000x reference)
#include <cuda_runtime.h>
#include <cuda_bf16.h>
#include <cuda_fp16.h>
#include <math.h>
#include <stdint.h>

#define L_LAYERS 4
#define T_SEQ    1024
#define B_BATCH  4
#define D_MODEL  1024
#define H_HEADS  16
#define DQK      64
#define FF_DIM   4096
#define NTOK     (T_SEQ * B_BATCH)   /* 4096 */
#define NBH      (B_BATCH * H_HEADS) /* 64 */

typedef __nv_bfloat16 bf16;
typedef __half fp16;

// ---------------- scratch (no allocations allowed) ----------------
__device__ float g_f  [(size_t)NTOK * D_MODEL];
__device__ float g_z  [(size_t)NTOK * D_MODEL];
__device__ float g_o  [(size_t)NTOK * D_MODEL];
__device__ float g_xb [(size_t)NTOK * D_MODEL];

__device__ bf16 g_xh[(size_t)NTOK * D_MODEL],  g_xl[(size_t)NTOK * D_MODEL];
__device__ fp16 g_zh[(size_t)NTOK * D_MODEL];
__device__ fp16 g_kh[(size_t)NTOK * D_MODEL];
__device__ fp16 g_qh[(size_t)NTOK * D_MODEL];
__device__ fp16 g_vh[(size_t)NTOK * D_MODEL];
__device__ bf16 g_h1h[(size_t)NTOK * FF_DIM],  g_h1l[(size_t)NTOK * FF_DIM];
__device__ fp16 g_sh[(size_t)NBH * T_SEQ * T_SEQ];   // 128 MB: logits then probs in-place
__device__ fp16 g_vth[(size_t)NTOK * D_MODEL];
// weight transposes+splits: wt[m][k]
__device__ bf16 g_w1th[(size_t)L_LAYERS * D_MODEL * FF_DIM], g_w1tl[(size_t)L_LAYERS * D_MODEL * FF_DIM];
__device__ bf16 g_w2th[(size_t)L_LAYERS * FF_DIM * D_MODEL], g_w2tl[(size_t)L_LAYERS * FF_DIM * D_MODEL];
__device__ fp16 g_wkth[(size_t)L_LAYERS * D_MODEL * D_MODEL];
__device__ fp16 g_wqth[(size_t)L_LAYERS * D_MODEL * D_MODEL];
__device__ fp16 g_wvth[(size_t)L_LAYERS * D_MODEL * D_MODEL];

// ---------------- helpers ----------------
__device__ __forceinline__ uint32_t smem_u32(const void* p) {
    uint32_t a;
    asm("{ .reg .u64 t; cvta.to.shared.u64 t, %1; cvt.u32.u64 %0, t; }" : "=r"(a) : "l"(p));
    return a;
}
__device__ __forceinline__ void cpa16(uint32_t s, const void* g) {
    asm volatile("cp.async.cg.shared.global [%0], [%1], 16;" :: "r"(s), "l"(g));
}
__device__ __forceinline__ void cpa_commit() {
    asm volatile("cp.async.commit_group;" ::: "memory");
}
__device__ __forceinline__ void cpa_wait2() {
    asm volatile("cp.async.wait_group 2;" ::: "memory");
}
__device__ __forceinline__ void cpa_wait1() {
    asm volatile("cp.async.wait_group 1;" ::: "memory");
}
__device__ __forceinline__ void cpa_wait0() {
    asm volatile("cp.async.wait_group 0;" ::: "memory");
}
__device__ __forceinline__ void ldsm4(uint32_t* r, uint32_t a) {
    asm volatile("ldmatrix.sync.aligned.m8n8.x4.shared.b16 {%0,%1,%2,%3}, [%4];"
                 : "=r"(r[0]), "=r"(r[1]), "=r"(r[2]), "=r"(r[3]) : "r"(a));
}

// ---- dtype-dispatched MMA / pack / round ----
template <typename T>
__device__ __forceinline__ void mma_t(float* d, const uint32_t* a, const uint32_t* b);
template <>
__device__ __forceinline__ void mma_t<bf16>(float* d, const uint32_t* a, const uint32_t* b) {
    asm volatile(
        "mma.sync.aligned.m16n8k16.row.col.f32.bf16.bf16.f32 "
        "{%0,%1,%2,%3}, {%4,%5,%6,%7}, {%8,%9}, {%0,%1,%2,%3};"
        : "+f"(d[0]), "+f"(d[1]), "+f"(d[2]), "+f"(d[3])
        : "r"(a[0]), "r"(a[1]), "r"(a[2]), "r"(a[3]), "r"(b[0]), "r"(b[1]));
}
template <>
__device__ __forceinline__ void mma_t<fp16>(float* d, const uint32_t* a, const uint32_t* b) {
    asm volatile(
        "mma.sync.aligned.m16n8k16.row.col.f32.f16.f16.f32 "
        "{%0,%1,%2,%3}, {%4,%5,%6,%7}, {%8,%9}, {%0,%1,%2,%3};"
        : "+f"(d[0]), "+f"(d[1]), "+f"(d[2]), "+f"(d[3])
        : "r"(a[0]), "r"(a[1]), "r"(a[2]), "r"(a[3]), "r"(b[0]), "r"(b[1]));
}
template <typename T> __device__ __forceinline__ uint32_t packpair(float a, float b);
template <> __device__ __forceinline__ uint32_t packpair<bf16>(float a, float b) {
    return ((uint32_t)__bfloat16_as_ushort(__float2bfloat16(b)) << 16)
         | __bfloat16_as_ushort(__float2bfloat16(a));
}
template <> __device__ __forceinline__ uint32_t packpair<fp16>(float a, float b) {
    __half2 p = __floats2half2_rn(a, b);
    return *reinterpret_cast<uint32_t*>(&p);
}
template <typename T> __device__ __forceinline__ float roundT(float v);
template <> __device__ __forceinline__ float roundT<bf16>(float v) {
    return __bfloat162float(__float2bfloat16(v));
}
template <> __device__ __forceinline__ float roundT<fp16>(float v) {
    return __half2float(__float2half_rn(v));
}
__device__ __forceinline__ void split_bf16(float v, bf16& h, bf16& l) {
    h = __float2bfloat16(v);
    l = __float2bfloat16(v - __bfloat162float(h));
}

// =====================================================================
// mma.sync GEMM, TERMS = 3 (hi/lo split: AhBh+AhBl+AlBh) or 1 (plain).
//   C[row,col] = act( (sum_k A[row,k]*B[col,k]) * scale? + bias[col]? )
// A: 128-row tile; B: BN-row tile; both K-major. BK=32, 3-stage cp.async.
// OUTMODE: 0 = fp32, 1 = T, 2 = T hi/lo split.
// Batched: bz = b*16 + h; per-operand offset = b*MulB + h*MulH.
// 256 threads: warps 2(M)x4(N); warp tile 64 x (BN/4).
// =====================================================================
template <int BN, int TERMS, int OUTMODE, bool RELU, bool HAS_BIAS, bool SCALED, typename T>
__global__ __launch_bounds__(256)
void gemm_mma(const T* __restrict__ Ah, const T* __restrict__ Al,
              long long strideA, long long aMulB, long long aMulH,
              const T* __restrict__ Bh, const T* __restrict__ Bl,
              long long strideB, long long bMulB, long long bMulH,
              const float* __restrict__ bias, int K,
              float* __restrict__ outF, T* __restrict__ outH, T* __restrict__ outL,
              long long strideC, long long cMulB, long long cMulH, float scale)
{
    constexpr int NT = BN / 32;           // n-tiles per warp
    constexpr int WN = BN / 4;            // warp N extent
    constexpr int AB = 128 * 80;          // one A plane (padded rows)
    constexpr int BB = BN * 80;
    constexpr int NP = (TERMS == 3) ? 2 : 1;   // planes per operand
    constexpr int STAGE = NP * (AB + BB);

    extern __shared__ __align__(16) char smemraw[];
    const uint32_t su = smem_u32(smemraw);

    const int tid  = threadIdx.x;
    const int lane = tid & 31, wid = tid >> 5;
    const int warpM = (wid & 1) * 64;
    const int warpN = (wid >> 1) * WN;
    const int row0 = blockIdx.y * 128;
    const int col0 = blockIdx.x * BN;
    const int bz = blockIdx.z, bb = bz >> 4, hh = bz & 15;
    const size_t aOff = (size_t)(bb * aMulB + hh * aMulH);
    const size_t bOff = (size_t)(bb * bMulB + hh * bMulH);

    auto load_stage = [&](int i) {
        const uint32_t sb = su + (uint32_t)((i % 3) * STAGE);
        const size_t k0 = (size_t)i * 32;
#pragma unroll
        for (int e = tid; e < 512; e += 256) {      // A: 128 rows x 4 x 16B
            const int r = e >> 2, c = e & 3;
            const size_t g = (size_t)(row0 + r) * strideA + aOff + k0 + c * 8;
            const uint32_t d = sb + (uint32_t)(r * 80 + c * 16);
            cpa16(d, Ah + g);
            if (TERMS == 3) cpa16(d + AB, Al + g);
        }
#pragma unroll
        for (int e = tid; e < BN * 4; e += 256) {   // B: BN rows x 4 x 16B
            const int r = e >> 2, c = e & 3;
            const size_t g = (size_t)(col0 + r) * strideB + bOff + k0 + c * 8;
            const uint32_t d = sb + (uint32_t)(NP * AB + r * 80 + c * 16);
            cpa16(d, Bh + g);
            if (TERMS == 3) cpa16(d + BB, Bl + g);
        }
        cpa_commit();
    };

    float d[4][NT][4];
#pragma unroll
    for (int mt = 0; mt < 4; mt++)
#pragma unroll
        for (int nt = 0; nt < NT; nt++)
#pragma unroll
            for (int j = 0; j < 4; j++) d[mt][nt][j] = 0.f;

    const int NC = K / 32;
    load_stage(0);
    if (NC > 1) load_stage(1);

    for (int i = 0; i < NC; i++) {
        if (i + 2 < NC)      { load_stage(i + 2); cpa_wait2(); }
        else if (i + 1 < NC) { cpa_wait1(); }
        else                 { cpa_wait0(); }
        __syncthreads();

        const uint32_t sa  = su + (uint32_t)((i % 3) * STAGE);
        const uint32_t sbh = sa + (uint32_t)(NP * AB);
#pragma unroll
        for (int ks = 0; ks < 2; ks++) {
            uint32_t ahf[4][4], alf[4][4];
#pragma unroll
            for (int mt = 0; mt < 4; mt++) {
                const uint32_t ad = sa + (uint32_t)((warpM + mt * 16 + (lane & 15)) * 80
                                                    + ks * 32 + (lane >> 4) * 16);
                ldsm4(ahf[mt], ad);
                if (TERMS == 3) ldsm4(alf[mt], ad + AB);
            }
            uint32_t bhf[NT][2], blf[NT][2];
#pragma unroll
            for (int pr = 0; pr < NT / 2; pr++) {
                const uint32_t bd = sbh + (uint32_t)((warpN + pr * 16 + (lane & 7)
                                                      + ((lane >> 4) & 1) * 8) * 80
                                                     + ks * 32 + ((lane >> 3) & 1) * 16);
                uint32_t t4[4];
                ldsm4(t4, bd);
                bhf[2 * pr][0] = t4[0]; bhf[2 * pr][1] = t4[1];
                bhf[2 * pr + 1][0] = t4[2]; bhf[2 * pr + 1][1] = t4[3];
                if (TERMS == 3) {
                    ldsm4(t4, bd + BB);
                    blf[2 * pr][0] = t4[0]; blf[2 * pr][1] = t4[1];
                    blf[2 * pr + 1][0] = t4[2]; blf[2 * pr + 1][1] = t4[3];
                }
            }
#pragma unroll
            for (int mt = 0; mt < 4; mt++)
#pragma unroll
                for (int nt = 0; nt < NT; nt++) {
                    mma_t<T>(d[mt][nt], ahf[mt], bhf[nt]);
                    if (TERMS == 3) {
                        mma_t<T>(d[mt][nt], ahf[mt], blf[nt]);
                        mma_t<T>(d[mt][nt], alf[mt], bhf[nt]);
                    }
                }
        }
        __syncthreads();
    }

    // ---- epilogue ----
    const size_t cOff = (size_t)(bb * cMulB + hh * cMulH);
#pragma unroll
    for (int mt = 0; mt < 4; mt++)
#pragma unroll
        for (int nt = 0; nt < NT; nt++) {
            const int r_ = row0 + warpM + mt * 16 + (lane >> 2);
            const int c_ = col0 + warpN + nt * 8 + (lane & 3) * 2;
            float bb0 = 0.f, bb1 = 0.f;
            if (HAS_BIAS) { bb0 = bias[c_]; bb1 = bias[c_ + 1]; }
            float v0 = d[mt][nt][0], v1 = d[mt][nt][1];
            float v2 = d[mt][nt][2], v3 = d[mt][nt][3];
            if (SCALED) { v0 *= scale; v1 *= scale; v2 *= scale; v3 *= scale; }
            if (HAS_BIAS) { v0 += bb0; v1 += bb1; v2 += bb0; v3 += bb1; }
            if (RELU) {
                v0 = fmaxf(v0, 0.f); v1 = fmaxf(v1, 0.f);
                v2 = fmaxf(v2, 0.f); v3 = fmaxf(v3, 0.f);
            }
            const size_t i0 = (size_t)r_ * strideC + cOff + c_;
            const size_t i1 = (size_t)(r_ + 8) * strideC + cOff + c_;
            if (OUTMODE == 2) {
                *(uint32_t*)(outH + i0) = packpair<T>(v0, v1);
                *(uint32_t*)(outL + i0) = packpair<T>(v0 - roundT<T>(v0), v1 - roundT<T>(v1));
                *(uint32_t*)(outH + i1) = packpair<T>(v2, v3);
                *(uint32_t*)(outL + i1) = packpair<T>(v2 - roundT<T>(v2), v3 - roundT<T>(v3));
            } else if (OUTMODE == 1) {
                *(uint32_t*)(outH + i0) = packpair<T>(v0, v1);
                *(uint32_t*)(outH + i1) = packpair<T>(v2, v3);
            } else {
                *(float2*)(outF + i0) = make_float2(v0, v1);
                *(float2*)(outF + i1) = make_float2(v2, v3);
            }
        }
}

// =====================================================================
// transpose + split: in[bz][R][C] fp32 -> outH(/outL) [bz][C][R] T
// =====================================================================
template <bool LO, typename T>
__global__ __launch_bounds__(256)
void transpose_split(const float* __restrict__ in, T* __restrict__ oh,
                     T* __restrict__ ol, int R, int C)
{
    __shared__ float t[32][33];
    const int bx = blockIdx.x * 32, by = blockIdx.y * 32;
    const size_t bbase = (size_t)blockIdx.z * R * C;
    const int x = threadIdx.x & 31, y = threadIdx.x >> 5;
#pragma unroll
    for (int j = 0; j < 32; j += 8)
        t[y + j][x] = in[bbase + (size_t)(by + y + j) * C + bx + x];
    __syncthreads();
#pragma unroll
    for (int j = 0; j < 32; j += 8) {
        float v = t[x][y + j];
        const size_t o = bbase + (size_t)(bx + y + j) * R + by + x;
        float h = roundT<T>(v);
        oh[o] = (T)h;
        if (LO) ol[o] = (T)(v - h);
    }
}

__global__ __launch_bounds__(256)
void split_only(const float* __restrict__ in, bf16* __restrict__ oh,
                bf16* __restrict__ ol, int n)
{
    int i = blockIdx.x * 256 + threadIdx.x;
    if (i < n) { bf16 h, l; split_bf16(in[i], h, l); oh[i] = h; ol[i] = l; }
}

// =====================================================================
// V gather-transpose: vh[(t*4+b)*1024 + h*64 + n] -> vt[bh][n][t]  (fp16)
// =====================================================================
__global__ __launch_bounds__(256)
void vtranspose(const fp16* __restrict__ vh, fp16* __restrict__ vth)
{
    __shared__ fp16 th[64][66];
    const int bh = blockIdx.z, b = bh >> 4, h = bh & 15;
    const int t0 = blockIdx.x * 64;
    for (int e = threadIdx.x; e < 4096; e += 256) {
        const int tt = e >> 6, n = e & 63;
        th[tt][n] = vh[((size_t)(t0 + tt) * 4 + b) * 1024 + h * 64 + n];
    }
    __syncthreads();
    for (int e = threadIdx.x; e < 4096; e += 256) {
        const int n = e >> 6, tt = e & 63;
        vth[((size_t)bh * 64 + n) * 1024 + t0 + tt] = th[tt][n];
    }
}

// =====================================================================
// Row softmax over last axis (1024); fp16 in/out, in-place.
// =====================================================================
__global__ __launch_bounds__(256)
void softmax_rows(fp16* __restrict__ S)
{
    __shared__ float redm[8], reds[8];
    __shared__ float bcm, bcs;
    const size_t row = (size_t)blockIdx.x * T_SEQ;
    const int tid = threadIdx.x;

    float v[4];
#pragma unroll
    for (int u = 0; u < 4; u++) v[u] = __half2float(S[row + tid + 256 * u]);
    float m = fmaxf(fmaxf(v[0], v[1]), fmaxf(v[2], v[3]));
#pragma unroll
    for (int o = 16; o; o >>= 1) m = fmaxf(m, __shfl_xor_sync(0xffffffffu, m, o));
    if ((tid & 31) == 0) redm[tid >> 5] = m;
    __syncthreads();
    if (tid == 0) {
        float mm = redm[0];
#pragma unroll
        for (int i = 1; i < 8; i++) mm = fmaxf(mm, redm[i]);
        bcm = mm;
    }
    __syncthreads();
    m = bcm;
    float s = 0.f;
#pragma unroll
    for (int u = 0; u < 4; u++) { v[u] = expf(v[u] - m); s += v[u]; }
#pragma unroll
    for (int o = 16; o; o >>= 1) s += __shfl_xor_sync(0xffffffffu, s, o);
    if ((tid & 31) == 0) reds[tid >> 5] = s;
    __syncthreads();
    if (tid == 0) {
        float ss = 0.f;
#pragma unroll
        for (int i = 0; i < 8; i++) ss += reds[i];
        bcs = 1.f / ss;
    }
    __syncthreads();
    const float inv = bcs;
#pragma unroll
    for (int u = 0; u < 4; u++)
        S[row + tid + 256 * u] = __float2half_rn(v[u] * inv);
}

// =====================================================================
// resnorm: out = ((x+fx)-mean)/(std_ddof1+eps)
// writes fp32 + T hi (and lo when WRITE_LO)
// =====================================================================
template <bool WRITE_LO, typename T>
__global__ __launch_bounds__(256)
void resnorm_k(const float* __restrict__ x, const float* __restrict__ fx,
               float* __restrict__ outF, T* __restrict__ outH, T* __restrict__ outL)
{
    __shared__ float reda[8], redb[8];
    __shared__ float bmu, binv;
    const size_t base = (size_t)blockIdx.x * D_MODEL;
    const int tid = threadIdx.x;

    float y[4];
    float s = 0.f, ss = 0.f;
#pragma unroll
    for (int u = 0; u < 4; u++) {
        float t = x[base + tid + 256 * u] + fx[base + tid + 256 * u];
        y[u] = t; s += t; ss += t * t;
    }
#pragma unroll
    for (int o = 16; o; o >>= 1) {
        s  += __shfl_xor_sync(0xffffffffu, s, o);
        ss += __shfl_xor_sync(0xffffffffu, ss, o);
    }
    if ((tid & 31) == 0) { reda[tid >> 5] = s; redb[tid >> 5] = ss; }
    __syncthreads();
    if (tid == 0) {
        float ts = 0.f, tss = 0.f;
#pragma unroll
        for (int i = 0; i < 8; i++) { ts += reda[i]; tss += redb[i]; }
        float mu  = ts / (float)D_MODEL;
        float var = (tss - (float)D_MODEL * mu * mu) * (1.f / (float)(D_MODEL - 1));
        bmu  = mu;
        binv = 1.f / (sqrtf(fmaxf(var, 0.f)) + 1e-6f);
    }
    __syncthreads();
    const float mu = bmu, inv = binv;
#pragma unroll
    for (int u = 0; u < 4; u++) {
        float v = (y[u] - mu) * inv;
        outF[base + tid + 256 * u] = v;
        float h = roundT<T>(v);
        outH[base + tid + 256 * u] = (T)h;
        if (WRITE_LO) outL[base + tid + 256 * u] = (T)(v - h);
    }
}

// =====================================================================
// Orchestration
// =====================================================================
#define GA(sym, var) cudaGetSymbolAddress((void**)&var, sym)

extern "C" void kernel_launch(void* const* d_in, const int* in_sizes, int n_in,
                              void* d_out, int out_size)
{
    (void)in_sizes; (void)n_in; (void)out_size;
    const float* x  = (const float*)d_in[0];
    const float* Wk = (const float*)d_in[2];
    const float* bk = (const float*)d_in[3];
    const float* Wq = (const float*)d_in[4];
    const float* bq = (const float*)d_in[5];
    const float* Wv = (const float*)d_in[6];
    const float* bv = (const float*)d_in[7];
    const float* W1 = (const float*)d_in[8];
    const float* b1 = (const float*)d_in[9];
    const float* W2 = (const float*)d_in[10];
    const float* b2 = (const float*)d_in[11];
    float* out = (float*)d_out;

    float *f, *z, *o, *xb;
    bf16 *xh, *xl, *h1h, *h1l, *w1th, *w1tl, *w2th, *w2tl;
    fp16 *zh, *kh, *qh, *vh, *sh, *vth, *wkth, *wqth, *wvth;
    GA(g_f, f); GA(g_z, z); GA(g_o, o); GA(g_xb, xb);
    GA(g_xh, xh); GA(g_xl, xl); GA(g_zh, zh);
    GA(g_kh, kh); GA(g_qh, qh); GA(g_vh, vh);
    GA(g_h1h, h1h); GA(g_h1l, h1l); GA(g_sh, sh); GA(g_vth, vth);
    GA(g_w1th, w1th); GA(g_w1tl, w1tl); GA(g_w2th, w2th); GA(g_w2tl, w2tl);
    GA(g_wkth, wkth); GA(g_wqth, wqth); GA(g_wvth, wvth);

    // smem: 3 stages * NP*(A(10240) + B(BN*80))
    const int SM128_3 = 3 * 2 * (10240 + 10240);   // 122880
    const int SM128_1 = 3 * (10240 + 10240);       // 61440
    const int SM64_1  = 3 * (10240 + 5120);        // 46080
    cudaFuncSetAttribute(gemm_mma<128, 3, 2, true,  true,  false, bf16>, cudaFuncAttributeMaxDynamicSharedMemorySize, SM128_3);
    cudaFuncSetAttribute(gemm_mma<128, 3, 0, true,  true,  false, bf16>, cudaFuncAttributeMaxDynamicSharedMemorySize, SM128_3);
    cudaFuncSetAttribute(gemm_mma<128, 1, 1, false, true,  false, fp16>, cudaFuncAttributeMaxDynamicSharedMemorySize, SM128_1);
    cudaFuncSetAttribute(gemm_mma<128, 1, 1, false, false, true,  fp16>, cudaFuncAttributeMaxDynamicSharedMemorySize, SM128_1);
    cudaFuncSetAttribute(gemm_mma<64,  1, 0, false, false, false, fp16>, cudaFuncAttributeMaxDynamicSharedMemorySize, SM64_1);

    // ---- per-launch weight transpose + split ----
    transpose_split<true,  bf16><<<dim3(FF_DIM / 32, D_MODEL / 32, L_LAYERS), 256>>>(W1, w1th, w1tl, D_MODEL, FF_DIM);
    transpose_split<true,  bf16><<<dim3(D_MODEL / 32, FF_DIM / 32, L_LAYERS), 256>>>(W2, w2th, w2tl, FF_DIM, D_MODEL);
    transpose_split<false, fp16><<<dim3(D_MODEL / 32, D_MODEL / 32, L_LAYERS), 256>>>(Wk, wkth, nullptr, D_MODEL, D_MODEL);
    transpose_split<false, fp16><<<dim3(D_MODEL / 32, D_MODEL / 32, L_LAYERS), 256>>>(Wq, wqth, nullptr, D_MODEL, D_MODEL);
    transpose_split<false, fp16><<<dim3(D_MODEL / 32, D_MODEL / 32, L_LAYERS), 256>>>(Wv, wvth, nullptr, D_MODEL, D_MODEL);
    split_only<<<(NTOK * D_MODEL) / 256, 256>>>(x, xh, xl, NTOK * D_MODEL);

    const size_t WS1 = (size_t)D_MODEL * FF_DIM;
    const size_t WSK = (size_t)D_MODEL * D_MODEL;
    const long long TT = (long long)T_SEQ * T_SEQ;   // 1048576
    const long long VT = 64LL * 1024LL;              // 65536

    for (int l = 0; l < L_LAYERS; l++) {
        const float* xinF = (l == 0) ? x : xb;

        // FF1: h1 = relu(x@W1+b1) -> split out [4096 x 4096]  (3-term bf16)
        gemm_mma<128, 3, 2, true, true, false, bf16><<<dim3(32, 32, 1), 256, SM128_3>>>(
            xh, xl, D_MODEL, 0, 0, w1th + l * WS1, w1tl + l * WS1, D_MODEL, 0, 0,
            b1 + (size_t)l * FF_DIM, D_MODEL, nullptr, h1h, h1l, FF_DIM, 0, 0, 1.f);
        // FF2: f = relu(h1@W2+b2) -> fp32 out [4096 x 1024]  (3-term bf16)
        gemm_mma<128, 3, 0, true, true, false, bf16><<<dim3(8, 32, 1), 256, SM128_3>>>(
            h1h, h1l, FF_DIM, 0, 0, w2th + l * WS1, w2tl + l * WS1, FF_DIM, 0, 0,
            b2 + (size_t)l * D_MODEL, FF_DIM, f, nullptr, nullptr, D_MODEL, 0, 0, 1.f);

        // z = resnorm(x + f): fp32 + fp16 hi
        resnorm_k<false, fp16><<<NTOK, 256>>>(xinF, f, z, zh, (fp16*)nullptr);

        // K, Q, V projections -> fp16 out [4096 x 1024]  (1-term fp16)
        gemm_mma<128, 1, 1, false, true, false, fp16><<<dim3(8, 32, 1), 256, SM128_1>>>(
            zh, nullptr, D_MODEL, 0, 0, wkth + l * WSK, nullptr, D_MODEL, 0, 0,
            bk + (size_t)l * D_MODEL, D_MODEL, nullptr, kh, nullptr, D_MODEL, 0, 0, 1.f);
        gemm_mma<128, 1, 1, false, true, false, fp16><<<dim3(8, 32, 1), 256, SM128_1>>>(
            zh, nullptr, D_MODEL, 0, 0, wqth + l * WSK, nullptr, D_MODEL, 0, 0,
            bq + (size_t)l * D_MODEL, D_MODEL, nullptr, qh, nullptr, D_MODEL, 0, 0, 1.f);
        gemm_mma<128, 1, 1, false, true, false, fp16><<<dim3(8, 32, 1), 256, SM128_1>>>(
            zh, nullptr, D_MODEL, 0, 0, wvth + l * WSK, nullptr, D_MODEL, 0, 0,
            bv + (size_t)l * D_MODEL, D_MODEL, nullptr, vh, nullptr, D_MODEL, 0, 0, 1.f);

        // vt[bh][n][t]
        vtranspose<<<dim3(16, 1, NBH), 256>>>(vh, vth);

        // S[bh][i][j] = (1/32) * sum_d K[i,d] Q[j,d]  -> fp16 logits (1-term)
        gemm_mma<128, 1, 1, false, false, true, fp16><<<dim3(8, 8, NBH), 256, SM128_1>>>(
            kh, nullptr, 4096, 1024, 64, qh, nullptr, 4096, 1024, 64,
            nullptr, DQK, nullptr, sh, nullptr, 1024, 16 * TT, TT, 0.03125f);

        softmax_rows<<<NBH * T_SEQ, 256>>>(sh);

        // O: o[(i*4+b)*1024 + h*64 + n] = sum_j P[bh][i][j] * vt[bh][n][j]  (1-term fp16)
        gemm_mma<64, 1, 0, false, false, false, fp16><<<dim3(1, 8, NBH), 256, SM64_1>>>(
            sh, nullptr, 1024, 16 * TT, TT, vth, nullptr, 1024, 16 * VT, VT,
            nullptr, T_SEQ, o, nullptr, nullptr, 4096, 1024, 64, 1.f);

        // x = resnorm(z + attn): fp32 + bf16 hi/lo (feeds next FF1)
        resnorm_k<true, bf16><<<NTOK, 256>>>(z, o, (l == L_LAYERS - 1) ? out : xb, xh, xl);
    }
}